// round 2
// baseline (speedup 1.0000x reference)
#include <cuda_runtime.h>
#include <math.h>

#define BB   512
#define MM   32
#define NAG  8
#define HH   256
#define NACT 16
#define HO   (HH * NAG)   // 2048

// d_out layout (tuple concatenated):
// action_prob [512,16] @ 0
// baseline    [512,1]  @ 8192
// hidstate    [512,256]@ 8704
// comm_out    [512,2048]@ 139776
#define ACT_OFF  0
#define BASE_OFF 8192
#define HID_OFF  8704
#define COMM_OFF 139776

// Scratch (no cudaMalloc allowed)
__device__ float g_csum[BB * HH];
__device__ int   g_cnt[MM];
__device__ int   g_list[MM * BB];

__global__ void k_zero() {
    if (threadIdx.x < MM) g_cnt[threadIdx.x] = 0;
}

// Per-example agent-sum + model-id grouping lists
__global__ void k_prep(const float* __restrict__ comm_in,
                       const int* __restrict__ mid) {
    int b = blockIdx.x;
    int h = threadIdx.x;
    const float* p = comm_in + b * NAG * HH + h;
    float s = 0.f;
#pragma unroll
    for (int a = 0; a < NAG; a++) s += p[a * HH];
    g_csum[b * HH + h] = s;
    if (h == 0) {
        int m = mid[b];
        int slot = atomicAdd(&g_cnt[m], 1);
        g_list[m * BB + slot] = b;
    }
}

// hid = tanh(enc + csum@Wc[m] + prev@Wr[m] + bc + br)
// grid (32 models, 2 col tiles of 128, 2 row-chunk groups), 128 threads
__global__ void k_hid(const float* __restrict__ prev_hid,
                      const float* __restrict__ Wc, const float* __restrict__ bc,
                      const float* __restrict__ Wr, const float* __restrict__ br,
                      const float* __restrict__ lut, const int* __restrict__ inp,
                      const float* __restrict__ enc_bias,
                      float* __restrict__ hid) {
    int m   = blockIdx.x;
    int col = blockIdx.y * 128 + threadIdx.x;
    int n   = g_cnt[m];
    if (n == 0) return;

    __shared__ float xc[8][HH];
    __shared__ float xp[8][HH];
    __shared__ int   rows[8];

    const float* WcP = Wc + m * HH * HH + col;
    const float* WrP = Wr + m * HH * HH + col;
    float biasv = bc[m * HH + col] + br[m * HH + col] + enc_bias[col];

    for (int base = blockIdx.z * 8; base < n; base += 16) {
        int R = n - base; if (R > 8) R = 8;
        // cooperative stage of up to 8 input rows
        for (int i = threadIdx.x; i < 8 * HH; i += 128) {
            int r = i >> 8;
            int k = i & (HH - 1);
            int rr  = (r < R) ? r : 0;
            int row = g_list[m * BB + base + rr];
            xc[r][k] = g_csum[row * HH + k];
            xp[r][k] = prev_hid[row * HH + k];
            if (k == 0) rows[r] = row;
        }
        __syncthreads();

        float acc[8];
#pragma unroll
        for (int r = 0; r < 8; r++) acc[r] = 0.f;

#pragma unroll 4
        for (int k = 0; k < HH; k++) {
            float wc = WcP[k * HH];
            float wr = WrP[k * HH];
#pragma unroll
            for (int r = 0; r < 8; r++) {
                acc[r] += xc[r][k] * wc;
                acc[r] += xp[r][k] * wr;
            }
        }

        for (int r = 0; r < R; r++) {
            int row = rows[r];
            float e = lut[inp[row] * HH + col];
            hid[row * HH + col] = tanhf(acc[r] + biasv + e);
        }
        __syncthreads();
    }
}

// comm_out = (hid@Wo[m] + bo[m]) / 7
// grid (32 models, 4 col tiles of 512, 2 row-chunk groups), 128 threads, 4 cols/thread
__global__ void k_commout(const float* __restrict__ hid,
                          const float* __restrict__ Wo, const float* __restrict__ bo,
                          float* __restrict__ comm) {
    int m    = blockIdx.x;
    int col0 = blockIdx.y * 512 + threadIdx.x * 4;
    int n    = g_cnt[m];
    if (n == 0) return;

    __shared__ float hs[8][HH];
    __shared__ int   rows[8];

    const float4* WoP = (const float4*)(Wo + (size_t)m * HH * HO + col0);
    float4 bov = *(const float4*)(bo + m * HO + col0);

    for (int base = blockIdx.z * 8; base < n; base += 16) {
        int R = n - base; if (R > 8) R = 8;
        for (int i = threadIdx.x; i < 8 * HH; i += 128) {
            int r = i >> 8;
            int k = i & (HH - 1);
            int rr  = (r < R) ? r : 0;
            int row = g_list[m * BB + base + rr];
            hs[r][k] = hid[row * HH + k];
            if (k == 0) rows[r] = row;
        }
        __syncthreads();

        float4 acc[8];
#pragma unroll
        for (int r = 0; r < 8; r++) { acc[r].x = acc[r].y = acc[r].z = acc[r].w = 0.f; }

#pragma unroll 2
        for (int k = 0; k < HH; k++) {
            float4 w = WoP[k * (HO / 4)];
#pragma unroll
            for (int r = 0; r < 8; r++) {
                float x = hs[r][k];
                acc[r].x += x * w.x;
                acc[r].y += x * w.y;
                acc[r].z += x * w.z;
                acc[r].w += x * w.w;
            }
        }

        for (int r = 0; r < R; r++) {
            int row = rows[r];
            float4 o;
            o.x = (acc[r].x + bov.x) / 7.0f;
            o.y = (acc[r].y + bov.y) / 7.0f;
            o.z = (acc[r].z + bov.z) / 7.0f;
            o.w = (acc[r].w + bov.w) / 7.0f;
            *(float4*)(comm + (size_t)row * HO + col0) = o;
        }
        __syncthreads();
    }
}

// action_prob = softmax(hid@Wa + ba), baseline = hid@Wb + bb
// 1 warp per example
__global__ void k_act(const float* __restrict__ hid, const int* __restrict__ mid,
                      const float* __restrict__ Wa, const float* __restrict__ ba,
                      const float* __restrict__ Wb, const float* __restrict__ bb,
                      float* __restrict__ act, float* __restrict__ base_out) {
    int b    = blockIdx.x;
    int lane = threadIdx.x;   // 32 threads
    int m    = mid[b];

    __shared__ float hsh[HH];
    for (int k = lane; k < HH; k += 32) hsh[k] = hid[b * HH + k];
    __syncwarp();

    float av = -1e30f;
    if (lane < NACT) {
        av = 0.f;
        const float* WaP = Wa + m * HH * NACT + lane;
#pragma unroll 4
        for (int k = 0; k < HH; k++) av += hsh[k] * WaP[k * NACT];
        av += ba[m * NACT + lane];
    }
    // softmax over 16 lanes (lanes 16..31 form their own inert group)
    float mx = av;
#pragma unroll
    for (int o = 8; o > 0; o >>= 1) mx = fmaxf(mx, __shfl_xor_sync(0xffffffffu, mx, o, 16));
    float ev = (lane < NACT) ? expf(av - mx) : 0.f;
    float sum = ev;
#pragma unroll
    for (int o = 8; o > 0; o >>= 1) sum += __shfl_xor_sync(0xffffffffu, sum, o, 16);
    if (lane < NACT) act[b * NACT + lane] = ev / sum;

    // baseline: full-warp strided dot
    const float* WbP = Wb + m * HH;
    float pv = 0.f;
    for (int k = lane; k < HH; k += 32) pv += hsh[k] * WbP[k];
#pragma unroll
    for (int o = 16; o > 0; o >>= 1) pv += __shfl_xor_sync(0xffffffffu, pv, o);
    if (lane == 0) base_out[b] = pv + bb[m];
}

extern "C" void kernel_launch(void* const* d_in, const int* in_sizes, int n_in,
                              void* d_out, int out_size) {
    const float* comm_in  = (const float*)d_in[0];
    const int*   inp      = (const int*)d_in[1];
    const float* prev_hid = (const float*)d_in[2];
    // d_in[3] = prev_cell (unused)
    const int*   mid      = (const int*)d_in[4];
    const float* Wc       = (const float*)d_in[5];
    const float* bc       = (const float*)d_in[6];
    const float* Wr       = (const float*)d_in[7];
    const float* br       = (const float*)d_in[8];
    const float* Wa       = (const float*)d_in[9];
    const float* ba       = (const float*)d_in[10];
    const float* Wb       = (const float*)d_in[11];
    const float* bb       = (const float*)d_in[12];
    const float* Wo       = (const float*)d_in[13];
    const float* bo       = (const float*)d_in[14];
    const float* lut      = (const float*)d_in[15];
    const float* enc_bias = (const float*)d_in[16];

    float* out  = (float*)d_out;
    float* act  = out + ACT_OFF;
    float* base = out + BASE_OFF;
    float* hid  = out + HID_OFF;
    float* comm = out + COMM_OFF;

    k_zero<<<1, 32>>>();
    k_prep<<<BB, HH>>>(comm_in, mid);
    k_hid<<<dim3(MM, 2, 2), 128>>>(prev_hid, Wc, bc, Wr, br, lut, inp, enc_bias, hid);
    k_commout<<<dim3(MM, 4, 2), 128>>>(hid, Wo, bo, comm);
    k_act<<<BB, 32>>>(hid, mid, Wa, ba, Wb, bb, act, base);
}

// round 4
// speedup vs baseline: 1.1602x; 1.1602x over previous
#include <cuda_runtime.h>
#include <math.h>

#define BB   512
#define MM   32
#define NAG  8
#define HH   256
#define NACT 16
#define HO   (HH * NAG)   // 2048

#define ACT_OFF  0
#define BASE_OFF 8192
#define HID_OFF  8704
#define COMM_OFF 139776

__device__ float g_csum[BB * HH];
__device__ int   g_cnt[MM];
__device__ int   g_list[MM * BB];

__global__ void k_zero() {
    if (threadIdx.x < MM) g_cnt[threadIdx.x] = 0;
}

// Per-example agent-sum + model-id grouping lists
__global__ void k_prep(const float* __restrict__ comm_in,
                       const int* __restrict__ mid) {
    int b = blockIdx.x;
    int h = threadIdx.x;
    const float* p = comm_in + b * NAG * HH + h;
    float s = 0.f;
#pragma unroll
    for (int a = 0; a < NAG; a++) s += p[a * HH];
    g_csum[b * HH + h] = s;
    if (h == 0) {
        int m = mid[b];
        int slot = atomicAdd(&g_cnt[m], 1);
        g_list[m * BB + slot] = b;
    }
}

// hid = tanh(enc + csum@Wc[m] + prev@Wr[m] + biases)
// grid (32, 2 col tiles of 128, 4 row groups), 128 threads
// K unrolled by 8 with batched weight loads for MLP.
__global__ void __launch_bounds__(128) k_hid(
                      const float* __restrict__ prev_hid,
                      const float* __restrict__ Wc, const float* __restrict__ bc,
                      const float* __restrict__ Wr, const float* __restrict__ br,
                      const float* __restrict__ lut, const int* __restrict__ inp,
                      const float* __restrict__ enc_bias,
                      float* __restrict__ hid) {
    int m   = blockIdx.x;
    int col = blockIdx.y * 128 + threadIdx.x;
    int n   = g_cnt[m];
    if (n == 0) return;

    __shared__ float xc[8][HH];
    __shared__ float xp[8][HH];
    __shared__ int   rows[8];

    const float* WcP = Wc + m * HH * HH + col;
    const float* WrP = Wr + m * HH * HH + col;
    float biasv = bc[m * HH + col] + br[m * HH + col] + enc_bias[col];

    for (int base = blockIdx.z * 8; base < n; base += 32) {
        int R = n - base; if (R > 8) R = 8;
        for (int i = threadIdx.x; i < 8 * HH; i += 128) {
            int r = i >> 8;
            int k = i & (HH - 1);
            int rr  = (r < R) ? r : 0;
            int row = g_list[m * BB + base + rr];
            xc[r][k] = g_csum[row * HH + k];
            xp[r][k] = prev_hid[row * HH + k];
            if (k == 0) rows[r] = row;
        }
        __syncthreads();

        float acc[8];
#pragma unroll
        for (int r = 0; r < 8; r++) acc[r] = 0.f;

        for (int k = 0; k < HH; k += 8) {
            float wc[8], wr[8];
#pragma unroll
            for (int u = 0; u < 8; u++) {
                wc[u] = WcP[(k + u) * HH];
                wr[u] = WrP[(k + u) * HH];
            }
#pragma unroll
            for (int u = 0; u < 8; u++) {
#pragma unroll
                for (int r = 0; r < 8; r++) {
                    acc[r] += xc[r][k + u] * wc[u];
                    acc[r] += xp[r][k + u] * wr[u];
                }
            }
        }

        for (int r = 0; r < R; r++) {
            int row = rows[r];
            float e = lut[inp[row] * HH + col];
            hid[row * HH + col] = tanhf(acc[r] + biasv + e);
        }
        __syncthreads();
    }
}

// comm_out = (hid@Wo[m] + bo[m]) / 7
// grid (32, 4 col tiles of 512, 2 row groups), 128 threads, float4 per thread.
// K unrolled by 8 with batched float4 weight loads: 8 LDG.128 in flight/thread.
__global__ void __launch_bounds__(128) k_commout(
                          const float* __restrict__ hid,
                          const float* __restrict__ Wo, const float* __restrict__ bo,
                          float* __restrict__ comm) {
    int m    = blockIdx.x;
    int col0 = blockIdx.y * 512 + threadIdx.x * 4;
    int n    = g_cnt[m];
    if (n == 0) return;

    __shared__ float hs[8][HH];
    __shared__ int   rows[8];

    const float4* WoP = (const float4*)(Wo + (size_t)m * HH * HO + col0);
    float4 bov = *(const float4*)(bo + m * HO + col0);

    for (int base = blockIdx.z * 8; base < n; base += 16) {
        int R = n - base; if (R > 8) R = 8;
        for (int i = threadIdx.x; i < 8 * HH; i += 128) {
            int r = i >> 8;
            int k = i & (HH - 1);
            int rr  = (r < R) ? r : 0;
            int row = g_list[m * BB + base + rr];
            hs[r][k] = hid[row * HH + k];
            if (k == 0) rows[r] = row;
        }
        __syncthreads();

        float4 acc[8];
#pragma unroll
        for (int r = 0; r < 8; r++) { acc[r].x = acc[r].y = acc[r].z = acc[r].w = 0.f; }

        for (int k = 0; k < HH; k += 8) {
            float4 w[8];
#pragma unroll
            for (int u = 0; u < 8; u++) w[u] = WoP[(k + u) * (HO / 4)];
#pragma unroll
            for (int u = 0; u < 8; u++) {
#pragma unroll
                for (int r = 0; r < 8; r++) {
                    float x = hs[r][k + u];
                    acc[r].x += x * w[u].x;
                    acc[r].y += x * w[u].y;
                    acc[r].z += x * w[u].z;
                    acc[r].w += x * w[u].w;
                }
            }
        }

        for (int r = 0; r < R; r++) {
            int row = rows[r];
            float4 o;
            o.x = (acc[r].x + bov.x) * (1.0f / 7.0f);
            o.y = (acc[r].y + bov.y) * (1.0f / 7.0f);
            o.z = (acc[r].z + bov.z) * (1.0f / 7.0f);
            o.w = (acc[r].w + bov.w) * (1.0f / 7.0f);
            *(float4*)(comm + (size_t)row * HO + col0) = o;
        }
        __syncthreads();
    }
}

// action_prob = softmax(hid@Wa + ba), baseline = hid@Wb + bb; 1 warp/example
__global__ void k_act(const float* __restrict__ hid, const int* __restrict__ mid,
                      const float* __restrict__ Wa, const float* __restrict__ ba,
                      const float* __restrict__ Wb, const float* __restrict__ bb,
                      float* __restrict__ act, float* __restrict__ base_out) {
    int b    = blockIdx.x;
    int lane = threadIdx.x;
    int m    = mid[b];

    __shared__ float hsh[HH];
    for (int k = lane; k < HH; k += 32) hsh[k] = hid[b * HH + k];
    __syncwarp();

    float av = -1e30f;
    if (lane < NACT) {
        av = 0.f;
        const float* WaP = Wa + m * HH * NACT + lane;
#pragma unroll 8
        for (int k = 0; k < HH; k++) av += hsh[k] * WaP[k * NACT];
        av += ba[m * NACT + lane];
    }
    float mx = av;
#pragma unroll
    for (int o = 8; o > 0; o >>= 1) mx = fmaxf(mx, __shfl_xor_sync(0xffffffffu, mx, o, 16));
    float ev = (lane < NACT) ? expf(av - mx) : 0.f;
    float sum = ev;
#pragma unroll
    for (int o = 8; o > 0; o >>= 1) sum += __shfl_xor_sync(0xffffffffu, sum, o, 16);
    if (lane < NACT) act[b * NACT + lane] = ev / sum;

    const float* WbP = Wb + m * HH;
    float pv = 0.f;
    for (int k = lane; k < HH; k += 32) pv += hsh[k] * WbP[k];
#pragma unroll
    for (int o = 16; o > 0; o >>= 1) pv += __shfl_xor_sync(0xffffffffu, pv, o);
    if (lane == 0) base_out[b] = pv + bb[m];
}

extern "C" void kernel_launch(void* const* d_in, const int* in_sizes, int n_in,
                              void* d_out, int out_size) {
    const float* comm_in  = (const float*)d_in[0];
    const int*   inp      = (const int*)d_in[1];
    const float* prev_hid = (const float*)d_in[2];
    const int*   mid      = (const int*)d_in[4];
    const float* Wc       = (const float*)d_in[5];
    const float* bc       = (const float*)d_in[6];
    const float* Wr       = (const float*)d_in[7];
    const float* br       = (const float*)d_in[8];
    const float* Wa       = (const float*)d_in[9];
    const float* ba       = (const float*)d_in[10];
    const float* Wb       = (const float*)d_in[11];
    const float* bb       = (const float*)d_in[12];
    const float* Wo       = (const float*)d_in[13];
    const float* bo       = (const float*)d_in[14];
    const float* lut      = (const float*)d_in[15];
    const float* enc_bias = (const float*)d_in[16];

    float* out  = (float*)d_out;
    float* act  = out + ACT_OFF;
    float* base = out + BASE_OFF;
    float* hid  = out + HID_OFF;
    float* comm = out + COMM_OFF;

    k_zero<<<1, 32>>>();
    k_prep<<<BB, HH>>>(comm_in, mid);
    k_hid<<<dim3(MM, 2, 4), 128>>>(prev_hid, Wc, bc, Wr, br, lut, inp, enc_bias, hid);
    k_commout<<<dim3(MM, 4, 2), 128>>>(hid, Wo, bo, comm);
    k_act<<<BB, 32>>>(hid, mid, Wa, ba, Wb, bb, act, base);
}

// round 5
// speedup vs baseline: 1.9632x; 1.6922x over previous
#include <cuda_runtime.h>
#include <math.h>

#define BB   512
#define MM   32
#define NAG  8
#define HH   256
#define NACT 16
#define HO   (HH * NAG)   // 2048

#define ACT_OFF  0
#define BASE_OFF 8192
#define HID_OFF  8704
#define COMM_OFF 139776

__device__ float g_csum[BB * HH];
__device__ float g_part[2 * BB * HH];   // partial Wc-path / Wr-path results
__device__ int   g_cnt[MM];
__device__ int   g_list[MM * BB];

__global__ void k_zero() {
    if (threadIdx.x < MM) g_cnt[threadIdx.x] = 0;
}

// Per-example agent-sum + model-id grouping lists
__global__ void k_prep(const float* __restrict__ comm_in,
                       const int* __restrict__ mid) {
    int b = blockIdx.x;
    int h = threadIdx.x;
    const float* p = comm_in + b * NAG * HH + h;
    float s = 0.f;
#pragma unroll
    for (int a = 0; a < NAG; a++) s += p[a * HH];
    g_csum[b * HH + h] = s;
    if (h == 0) {
        int m = mid[b];
        int slot = atomicAdd(&g_cnt[m], 1);
        g_list[m * BB + slot] = b;
    }
}

// Partial GEMMs for hid: y>>1 selects (Wc,csum) vs (Wr,prev_hid).
// grid (32, 4, 4), 128 threads; 8 rows/thread, 1 col/thread.
__global__ void __launch_bounds__(128) k_hidmm(
                      const float* __restrict__ prev_hid,
                      const float* __restrict__ Wc,
                      const float* __restrict__ Wr) {
    int m = blockIdx.x;
    int n = g_cnt[m];
    if (n == 0) return;
    int mat = blockIdx.y >> 1;
    int col = (blockIdx.y & 1) * 128 + threadIdx.x;

    const float* W = (mat ? Wr : Wc) + m * HH * HH + col;
    const float* X = mat ? prev_hid : g_csum;
    float* P = g_part + mat * (BB * HH);

    __shared__ float xs[8][HH];
    __shared__ int   rows[8];

    for (int base = blockIdx.z * 8; base < n; base += 8 * gridDim.z) {
        int R = n - base; if (R > 8) R = 8;
        for (int i = threadIdx.x; i < 8 * HH; i += 128) {
            int r = i >> 8;
            int k = i & (HH - 1);
            int rr  = (r < R) ? r : 0;
            int row = g_list[m * BB + base + rr];
            xs[r][k] = X[row * HH + k];
            if (k == 0) rows[r] = row;
        }
        __syncthreads();

        float acc[8];
#pragma unroll
        for (int r = 0; r < 8; r++) acc[r] = 0.f;

        for (int k = 0; k < HH; k += 8) {
            float w[8];
#pragma unroll
            for (int u = 0; u < 8; u++) w[u] = W[(k + u) * HH];
#pragma unroll
            for (int u = 0; u < 8; u++) {
#pragma unroll
                for (int r = 0; r < 8; r++) acc[r] += xs[r][k + u] * w[u];
            }
        }

        for (int r = 0; r < R; r++) P[rows[r] * HH + col] = acc[r];
        __syncthreads();
    }
}

// hid = tanh(partC + partR + bc + br + enc_bias + lut[inp])
__global__ void k_hidep(const int* __restrict__ mid,
                        const float* __restrict__ bc, const float* __restrict__ br,
                        const float* __restrict__ lut, const int* __restrict__ inp,
                        const float* __restrict__ enc_bias,
                        float* __restrict__ hid) {
    int b = blockIdx.x;
    int c = threadIdx.x;
    int m = mid[b];
    float v = g_part[b * HH + c] + g_part[BB * HH + b * HH + c]
            + bc[m * HH + c] + br[m * HH + c]
            + enc_bias[c] + lut[inp[b] * HH + c];
    hid[b * HH + c] = tanhf(v);
}

// comm_out = (hid@Wo[m] + bo[m]) / 7
// grid (32, 8 col-tiles of 256, 4 row groups), 128 threads, float2/thread.
__global__ void __launch_bounds__(128) k_commout(
                          const float* __restrict__ hid,
                          const float* __restrict__ Wo, const float* __restrict__ bo,
                          float* __restrict__ comm) {
    int m    = blockIdx.x;
    int n    = g_cnt[m];
    if (n == 0) return;
    int col0 = blockIdx.y * 256 + threadIdx.x * 2;

    __shared__ float hs[8][HH];
    __shared__ int   rows[8];

    const float2* WoP = (const float2*)(Wo + (size_t)m * HH * HO + col0);
    float2 bov = *(const float2*)(bo + m * HO + col0);

    for (int base = blockIdx.z * 8; base < n; base += 8 * gridDim.z) {
        int R = n - base; if (R > 8) R = 8;
        for (int i = threadIdx.x; i < 8 * HH; i += 128) {
            int r = i >> 8;
            int k = i & (HH - 1);
            int rr  = (r < R) ? r : 0;
            int row = g_list[m * BB + base + rr];
            hs[r][k] = hid[row * HH + k];
            if (k == 0) rows[r] = row;
        }
        __syncthreads();

        float2 acc[8];
#pragma unroll
        for (int r = 0; r < 8; r++) { acc[r].x = 0.f; acc[r].y = 0.f; }

        for (int k = 0; k < HH; k += 8) {
            float2 w[8];
#pragma unroll
            for (int u = 0; u < 8; u++) w[u] = WoP[(k + u) * (HO / 2)];
#pragma unroll
            for (int u = 0; u < 8; u++) {
#pragma unroll
                for (int r = 0; r < 8; r++) {
                    float x = hs[r][k + u];
                    acc[r].x += x * w[u].x;
                    acc[r].y += x * w[u].y;
                }
            }
        }

        for (int r = 0; r < R; r++) {
            int row = rows[r];
            float2 o;
            o.x = (acc[r].x + bov.x) * (1.0f / 7.0f);
            o.y = (acc[r].y + bov.y) * (1.0f / 7.0f);
            *(float2*)(comm + (size_t)row * HO + col0) = o;
        }
        __syncthreads();
    }
}

// action_prob = softmax(hid@Wa + ba), baseline = hid@Wb + bb
// 128 threads/example: action dot K-split 8-way (t = act + 16*kc), smem reduce.
__global__ void __launch_bounds__(128) k_act(
                      const float* __restrict__ hid, const int* __restrict__ mid,
                      const float* __restrict__ Wa, const float* __restrict__ ba,
                      const float* __restrict__ Wb, const float* __restrict__ bb,
                      float* __restrict__ act, float* __restrict__ base_out) {
    int b = blockIdx.x;
    int t = threadIdx.x;
    int m = mid[b];

    __shared__ float hsh[HH];
    __shared__ float sp[8][NACT];
    __shared__ float sb[4];

    for (int k = t; k < HH; k += 128) hsh[k] = hid[b * HH + k];
    __syncthreads();

    // action partial: act index a = t & 15, k-chunk kc = t >> 4 (8 chunks of 32)
    {
        int a  = t & 15;
        int kc = t >> 4;
        const float* WaP = Wa + m * HH * NACT + a;
        float s = 0.f;
#pragma unroll 8
        for (int j = 0; j < 32; j++) {
            int k = kc * 32 + j;
            s += hsh[k] * WaP[k * NACT];
        }
        sp[kc][a] = s;
    }

    // baseline: 2 MACs/thread + warp/block reduce
    {
        const float* WbP = Wb + m * HH;
        float pv = hsh[t] * WbP[t] + hsh[t + 128] * WbP[t + 128];
#pragma unroll
        for (int o = 16; o > 0; o >>= 1) pv += __shfl_xor_sync(0xffffffffu, pv, o);
        if ((t & 31) == 0) sb[t >> 5] = pv;
    }
    __syncthreads();

    if (t < NACT) {
        float v = ba[m * NACT + t];
#pragma unroll
        for (int kc = 0; kc < 8; kc++) v += sp[kc][t];
        // softmax across lanes 0..15 of warp 0
        float mx = v;
#pragma unroll
        for (int o = 8; o > 0; o >>= 1) mx = fmaxf(mx, __shfl_xor_sync(0xffffu, mx, o, 16));
        float ev = expf(v - mx);
        float sum = ev;
#pragma unroll
        for (int o = 8; o > 0; o >>= 1) sum += __shfl_xor_sync(0xffffu, sum, o, 16);
        act[b * NACT + t] = ev / sum;
    }
    if (t == 16 + NACT) {} // no-op
    if (t == 0) base_out[b] = sb[0] + sb[1] + sb[2] + sb[3] + bb[m];
}

extern "C" void kernel_launch(void* const* d_in, const int* in_sizes, int n_in,
                              void* d_out, int out_size) {
    const float* comm_in  = (const float*)d_in[0];
    const int*   inp      = (const int*)d_in[1];
    const float* prev_hid = (const float*)d_in[2];
    const int*   mid      = (const int*)d_in[4];
    const float* Wc       = (const float*)d_in[5];
    const float* bc       = (const float*)d_in[6];
    const float* Wr       = (const float*)d_in[7];
    const float* br       = (const float*)d_in[8];
    const float* Wa       = (const float*)d_in[9];
    const float* ba       = (const float*)d_in[10];
    const float* Wb       = (const float*)d_in[11];
    const float* bb       = (const float*)d_in[12];
    const float* Wo       = (const float*)d_in[13];
    const float* bo       = (const float*)d_in[14];
    const float* lut      = (const float*)d_in[15];
    const float* enc_bias = (const float*)d_in[16];

    float* out  = (float*)d_out;
    float* act  = out + ACT_OFF;
    float* base = out + BASE_OFF;
    float* hid  = out + HID_OFF;
    float* comm = out + COMM_OFF;

    k_zero<<<1, 32>>>();
    k_prep<<<BB, HH>>>(comm_in, mid);
    k_hidmm<<<dim3(MM, 4, 4), 128>>>(prev_hid, Wc, Wr);
    k_hidep<<<BB, HH>>>(mid, bc, br, lut, inp, enc_bias, hid);
    k_commout<<<dim3(MM, 8, 4), 128>>>(hid, Wo, bo, comm);
    k_act<<<BB, 128>>>(hid, mid, Wa, ba, Wb, bb, act, base);
}

// round 7
// speedup vs baseline: 2.3348x; 1.1892x over previous
#include <cuda_runtime.h>
#include <math.h>

#define BB   512
#define MM   32
#define NAG  8
#define HH   256
#define KH   128          // K half
#define NACT 16
#define HO   (HH * NAG)   // 2048

#define ACT_OFF  0
#define BASE_OFF 8192
#define HID_OFF  8704
#define COMM_OFF 139776

__device__ float g_csum[BB * HH];
__device__ float g_part[4 * BB * HH];    // hid partials: (mat*2+khalf)
__device__ float g_cpart[2 * BB * HO];   // comm_out partials per khalf (8MB)
__device__ int   g_cnt[MM];
__device__ int   g_list[MM * BB];

__global__ void k_zero() {
    if (threadIdx.x < MM) g_cnt[threadIdx.x] = 0;
}

// Per-example agent-sum + model-id grouping lists
__global__ void k_prep(const float* __restrict__ comm_in,
                       const int* __restrict__ mid) {
    int b = blockIdx.x;
    int h = threadIdx.x;
    const float* p = comm_in + b * NAG * HH + h;
    float s = 0.f;
#pragma unroll
    for (int a = 0; a < NAG; a++) s += p[a * HH];
    g_csum[b * HH + h] = s;
    if (h == 0) {
        int m = mid[b];
        int slot = atomicAdd(&g_cnt[m], 1);
        g_list[m * BB + slot] = b;
    }
}

// hid partial GEMMs, K-split 2-way.
// grid (32, 4, 4): y = mat*2 + coltile ; z = rowgroup*2 + khalf. 128 threads.
__global__ void __launch_bounds__(128) k_hidmm(
                      const float* __restrict__ prev_hid,
                      const float* __restrict__ Wc,
                      const float* __restrict__ Wr) {
    int m = blockIdx.x;
    int n = g_cnt[m];
    if (n == 0) return;
    int mat = blockIdx.y >> 1;
    int col = (blockIdx.y & 1) * 128 + threadIdx.x;
    int rg  = blockIdx.z >> 1;
    int kh  = blockIdx.z & 1;

    const float* W = (mat ? Wr : Wc) + m * HH * HH + kh * KH * HH + col;
    const float* X = (mat ? prev_hid : g_csum);
    float* P = g_part + (mat * 2 + kh) * (BB * HH);

    __shared__ float xs[8][KH];
    __shared__ int   rows[8];

    for (int base = rg * 8; base < n; base += 16) {
        int R = n - base; if (R > 8) R = 8;
        for (int i = threadIdx.x; i < 8 * KH; i += 128) {
            int r = i >> 7;
            int k = i & (KH - 1);
            int rr  = (r < R) ? r : 0;
            int row = g_list[m * BB + base + rr];
            xs[r][k] = X[row * HH + kh * KH + k];
            if (k == 0) rows[r] = row;
        }
        __syncthreads();

        float acc[8];
#pragma unroll
        for (int r = 0; r < 8; r++) acc[r] = 0.f;

        for (int k = 0; k < KH; k += 8) {
            float w[8];
#pragma unroll
            for (int u = 0; u < 8; u++) w[u] = W[(k + u) * HH];
#pragma unroll
            for (int u = 0; u < 8; u++) {
#pragma unroll
                for (int r = 0; r < 8; r++) acc[r] += xs[r][k + u] * w[u];
            }
        }

        for (int r = 0; r < R; r++) P[rows[r] * HH + col] = acc[r];
        __syncthreads();
    }
}

// Fused: hid = tanh(sum of 4 partials + biases + lut); then action softmax + baseline.
__global__ void __launch_bounds__(128) k_hidact(
                      const int* __restrict__ mid,
                      const float* __restrict__ bc, const float* __restrict__ br,
                      const float* __restrict__ lut, const int* __restrict__ inp,
                      const float* __restrict__ enc_bias,
                      const float* __restrict__ Wa, const float* __restrict__ ba,
                      const float* __restrict__ Wb, const float* __restrict__ bb,
                      float* __restrict__ hid,
                      float* __restrict__ act, float* __restrict__ base_out) {
    int b = blockIdx.x;
    int t = threadIdx.x;
    int m = mid[b];

    __shared__ float hsh[HH];
    __shared__ float sp[8][NACT];
    __shared__ float sb[4];

#pragma unroll
    for (int c = t; c < HH; c += 128) {
        float v = g_part[b * HH + c]
                + g_part[1 * BB * HH + b * HH + c]
                + g_part[2 * BB * HH + b * HH + c]
                + g_part[3 * BB * HH + b * HH + c]
                + bc[m * HH + c] + br[m * HH + c]
                + enc_bias[c] + lut[inp[b] * HH + c];
        float h = tanhf(v);
        hid[b * HH + c] = h;
        hsh[c] = h;
    }
    __syncthreads();

    // action partial: a = t & 15, kc = t >> 4 (8 chunks of 32)
    {
        int a  = t & 15;
        int kc = t >> 4;
        const float* WaP = Wa + m * HH * NACT + a;
        float s = 0.f;
#pragma unroll 8
        for (int j = 0; j < 32; j++) {
            int k = kc * 32 + j;
            s += hsh[k] * WaP[k * NACT];
        }
        sp[kc][a] = s;
    }
    // baseline partial
    {
        const float* WbP = Wb + m * HH;
        float pv = hsh[t] * WbP[t] + hsh[t + 128] * WbP[t + 128];
#pragma unroll
        for (int o = 16; o > 0; o >>= 1) pv += __shfl_xor_sync(0xffffffffu, pv, o);
        if ((t & 31) == 0) sb[t >> 5] = pv;
    }
    __syncthreads();

    if (t < NACT) {
        float v = ba[m * NACT + t];
#pragma unroll
        for (int kc = 0; kc < 8; kc++) v += sp[kc][t];
        float mx = v;
#pragma unroll
        for (int o = 8; o > 0; o >>= 1) mx = fmaxf(mx, __shfl_xor_sync(0xffffu, mx, o, 16));
        float ev = expf(v - mx);
        float sum = ev;
#pragma unroll
        for (int o = 8; o > 0; o >>= 1) sum += __shfl_xor_sync(0xffffu, sum, o, 16);
        act[b * NACT + t] = ev / sum;
    }
    if (t == 0) base_out[b] = sb[0] + sb[1] + sb[2] + sb[3] + bb[m];
}

// comm_out partial GEMM, K-split 2-way.
// grid (32, 8, 4): y = col-tile of 256; z = khalf*2 + rowgroup. 128 thr, float2/thread.
__global__ void __launch_bounds__(128) k_commout(
                          const float* __restrict__ hid,
                          const float* __restrict__ Wo) {
    int m = blockIdx.x;
    int n = g_cnt[m];
    if (n == 0) return;
    int col0 = blockIdx.y * 256 + threadIdx.x * 2;
    int kh   = blockIdx.z >> 1;
    int rg   = blockIdx.z & 1;

    __shared__ float hs[8][KH];
    __shared__ int   rows[8];

    const float2* WoP = (const float2*)(Wo + (size_t)m * HH * HO + (size_t)kh * KH * HO + col0);
    float* P = g_cpart + (size_t)kh * BB * HO;

    for (int base = rg * 8; base < n; base += 16) {
        int R = n - base; if (R > 8) R = 8;
        for (int i = threadIdx.x; i < 8 * KH; i += 128) {
            int r = i >> 7;
            int k = i & (KH - 1);
            int rr  = (r < R) ? r : 0;
            int row = g_list[m * BB + base + rr];
            hs[r][k] = hid[row * HH + kh * KH + k];
            if (k == 0) rows[r] = row;
        }
        __syncthreads();

        float2 acc[8];
#pragma unroll
        for (int r = 0; r < 8; r++) { acc[r].x = 0.f; acc[r].y = 0.f; }

        for (int k = 0; k < KH; k += 8) {
            float2 w[8];
#pragma unroll
            for (int u = 0; u < 8; u++) w[u] = WoP[(k + u) * (HO / 2)];
#pragma unroll
            for (int u = 0; u < 8; u++) {
#pragma unroll
                for (int r = 0; r < 8; r++) {
                    float x = hs[r][k + u];
                    acc[r].x += x * w[u].x;
                    acc[r].y += x * w[u].y;
                }
            }
        }

        for (int r = 0; r < R; r++) {
            int row = rows[r];
            *(float2*)(P + (size_t)row * HO + col0) = acc[r];
        }
        __syncthreads();
    }
}

// comm epilogue: comm = (p0 + p1 + bo[m]) / 7. grid (1024, 256), float4/thread.
__global__ void __launch_bounds__(256) k_commep(
                        const int* __restrict__ mid,
                        const float* __restrict__ bo,
                        float* __restrict__ comm) {
    int row  = blockIdx.x >> 1;               // example
    int half = blockIdx.x & 1;                // which half of the 2048 cols
    int col  = half * (HO / 2) + threadIdx.x * 4;
    int m    = mid[row];

    size_t off = (size_t)row * HO + col;
    float4 p0 = *(const float4*)(g_cpart + off);
    float4 p1 = *(const float4*)(g_cpart + (size_t)BB * HO + off);
    float4 bv = *(const float4*)(bo + m * HO + col);
    float4 o;
    o.x = (p0.x + p1.x + bv.x) * (1.0f / 7.0f);
    o.y = (p0.y + p1.y + bv.y) * (1.0f / 7.0f);
    o.z = (p0.z + p1.z + bv.z) * (1.0f / 7.0f);
    o.w = (p0.w + p1.w + bv.w) * (1.0f / 7.0f);
    *(float4*)(comm + off) = o;
}

extern "C" void kernel_launch(void* const* d_in, const int* in_sizes, int n_in,
                              void* d_out, int out_size) {
    const float* comm_in  = (const float*)d_in[0];
    const int*   inp      = (const int*)d_in[1];
    const float* prev_hid = (const float*)d_in[2];
    const int*   mid      = (const int*)d_in[4];
    const float* Wc       = (const float*)d_in[5];
    const float* bc       = (const float*)d_in[6];
    const float* Wr       = (const float*)d_in[7];
    const float* br       = (const float*)d_in[8];
    const float* Wa       = (const float*)d_in[9];
    const float* ba       = (const float*)d_in[10];
    const float* Wb       = (const float*)d_in[11];
    const float* bb       = (const float*)d_in[12];
    const float* Wo       = (const float*)d_in[13];
    const float* bo       = (const float*)d_in[14];
    const float* lut      = (const float*)d_in[15];
    const float* enc_bias = (const float*)d_in[16];

    float* out  = (float*)d_out;
    float* act  = out + ACT_OFF;
    float* base = out + BASE_OFF;
    float* hid  = out + HID_OFF;
    float* comm = out + COMM_OFF;

    k_zero<<<1, 32>>>();
    k_prep<<<BB, HH>>>(comm_in, mid);
    k_hidmm<<<dim3(MM, 4, 4), 128>>>(prev_hid, Wc, Wr);
    k_hidact<<<BB, 128>>>(mid, bc, br, lut, inp, enc_bias,
                          Wa, ba, Wb, bb, hid, act, base);
    k_commout<<<dim3(MM, 8, 4), 128>>>(hid, Wo);
    k_commep<<<2 * BB, 256>>>(mid, bo, comm);
}

// round 8
// speedup vs baseline: 2.6754x; 1.1459x over previous
#include <cuda_runtime.h>
#include <math.h>

#define BB   512
#define MM   32
#define NAG  8
#define HH   256
#define KQ   64           // K quarter
#define NACT 16
#define HO   (HH * NAG)   // 2048

#define ACT_OFF  0
#define BASE_OFF 8192
#define HID_OFF  8704
#define COMM_OFF 139776

__device__ float g_csum[BB * HH];
__device__ float g_part[8 * BB * HH];    // hid partials: (mat*4 + kq)
__device__ float g_cpart[4 * BB * HO];   // comm partials per kq (16MB)
__device__ int   g_cnt[MM];
__device__ int   g_list[MM * BB];

__global__ void k_zero() {
    if (threadIdx.x < MM) g_cnt[threadIdx.x] = 0;
}

// Per-example agent-sum + model-id grouping lists
__global__ void k_prep(const float* __restrict__ comm_in,
                       const int* __restrict__ mid) {
    int b = blockIdx.x;
    int h = threadIdx.x;
    const float* p = comm_in + b * NAG * HH + h;
    float s = 0.f;
#pragma unroll
    for (int a = 0; a < NAG; a++) s += p[a * HH];
    g_csum[b * HH + h] = s;
    if (h == 0) {
        int m = mid[b];
        int slot = atomicAdd(&g_cnt[m], 1);
        g_list[m * BB + slot] = b;
    }
}

// hid partial GEMMs. grid (32, mat*2+coltile, kq). 128 threads, 1 col/thread.
// Each block loops over ALL row chunks of its group -> weight slab (32KB)
// crosses L2 once, repeat chunks hit L1.
__global__ void __launch_bounds__(128) k_hidmm(
                      const float* __restrict__ prev_hid,
                      const float* __restrict__ Wc,
                      const float* __restrict__ Wr) {
    int m = blockIdx.x;
    int n = g_cnt[m];
    if (n == 0) return;
    int mat = blockIdx.y >> 1;
    int col = (blockIdx.y & 1) * 128 + threadIdx.x;
    int kq  = blockIdx.z;

    const float* W = (mat ? Wr : Wc) + m * HH * HH + kq * KQ * HH + col;
    const float* X = (mat ? prev_hid : g_csum) + kq * KQ;
    float* P = g_part + (mat * 4 + kq) * (BB * HH);

    __shared__ float xs[8][KQ];
    __shared__ int   rows[8];

    for (int base = 0; base < n; base += 8) {
        int R = n - base; if (R > 8) R = 8;
        for (int i = threadIdx.x; i < 8 * KQ; i += 128) {
            int r = i >> 6;
            int k = i & (KQ - 1);
            int rr  = (r < R) ? r : 0;
            int row = g_list[m * BB + base + rr];
            xs[r][k] = X[row * HH + k];
            if (k == 0) rows[r] = row;
        }
        __syncthreads();

        float acc[8];
#pragma unroll
        for (int r = 0; r < 8; r++) acc[r] = 0.f;

        for (int k = 0; k < KQ; k += 8) {
            float w[8];
#pragma unroll
            for (int u = 0; u < 8; u++) w[u] = W[(k + u) * HH];
#pragma unroll
            for (int u = 0; u < 8; u++) {
#pragma unroll
                for (int r = 0; r < 8; r++) acc[r] += xs[r][k + u] * w[u];
            }
        }

        for (int r = 0; r < R; r++) P[rows[r] * HH + col] = acc[r];
        __syncthreads();
    }
}

// Fused: hid = tanh(sum of 8 partials + biases + lut); action softmax + baseline.
// Action dot uses coalesced float4 Wa loads: thread = (a-quartet aq, k-chunk kc).
__global__ void __launch_bounds__(128) k_hidact(
                      const int* __restrict__ mid,
                      const float* __restrict__ bc, const float* __restrict__ br,
                      const float* __restrict__ lut, const int* __restrict__ inp,
                      const float* __restrict__ enc_bias,
                      const float* __restrict__ Wa, const float* __restrict__ ba,
                      const float* __restrict__ Wb, const float* __restrict__ bb,
                      float* __restrict__ hid,
                      float* __restrict__ act, float* __restrict__ base_out) {
    int b = blockIdx.x;
    int t = threadIdx.x;
    int m = mid[b];

    __shared__ float hsh[HH];
    __shared__ float sps[32 * 16];   // [kc][a] partials (flat)
    __shared__ float sb[4];

#pragma unroll
    for (int c = t; c < HH; c += 128) {
        float v = bc[m * HH + c] + br[m * HH + c]
                + enc_bias[c] + lut[inp[b] * HH + c];
#pragma unroll
        for (int s = 0; s < 8; s++) v += g_part[s * (BB * HH) + b * HH + c];
        float h = tanhf(v);
        hid[b * HH + c] = h;
        hsh[c] = h;
    }
    __syncthreads();

    // action partials: aq = t&3 (4 actions), kc = t>>2 (8 k's each)
    {
        int aq = t & 3;
        int kc = t >> 2;
        const float4* WaP = (const float4*)(Wa + m * HH * NACT + aq * 4);
        float4 a4 = make_float4(0.f, 0.f, 0.f, 0.f);
#pragma unroll
        for (int j = 0; j < 8; j++) {
            int k = kc * 8 + j;
            float4 w = WaP[k * 4];          // Wa[k][aq*4 .. aq*4+3]
            float x = hsh[k];
            a4.x += x * w.x; a4.y += x * w.y; a4.z += x * w.z; a4.w += x * w.w;
        }
        *(float4*)&sps[kc * 16 + aq * 4] = a4;
    }
    // baseline partial
    {
        const float* WbP = Wb + m * HH;
        float pv = hsh[t] * WbP[t] + hsh[t + 128] * WbP[t + 128];
#pragma unroll
        for (int o = 16; o > 0; o >>= 1) pv += __shfl_xor_sync(0xffffffffu, pv, o);
        if ((t & 31) == 0) sb[t >> 5] = pv;
    }
    __syncthreads();

    if (t < NACT) {
        float v = ba[m * NACT + t];
#pragma unroll
        for (int kc = 0; kc < 32; kc++) v += sps[kc * 16 + t];
        float mx = v;
#pragma unroll
        for (int o = 8; o > 0; o >>= 1) mx = fmaxf(mx, __shfl_xor_sync(0xffffu, mx, o, 16));
        float ev = expf(v - mx);
        float sum = ev;
#pragma unroll
        for (int o = 8; o > 0; o >>= 1) sum += __shfl_xor_sync(0xffffu, sum, o, 16);
        act[b * NACT + t] = ev / sum;
    }
    if (t == 0) base_out[b] = sb[0] + sb[1] + sb[2] + sb[3] + bb[m];
}

// comm partial GEMM. grid (32, 4 col-tiles of 512, 4 kq). 256 threads, float2/thread.
// Block loops over ALL row chunks -> 128KB weight slab crosses L2 once, L1 repeats.
__global__ void __launch_bounds__(256) k_commout(
                          const float* __restrict__ hid,
                          const float* __restrict__ Wo) {
    int m = blockIdx.x;
    int n = g_cnt[m];
    if (n == 0) return;
    int col0 = blockIdx.y * 512 + threadIdx.x * 2;
    int kq   = blockIdx.z;

    __shared__ float hs[8][KQ];
    __shared__ int   rows[8];

    const float2* WoP = (const float2*)(Wo + (size_t)m * HH * HO + (size_t)kq * KQ * HO + col0);
    float* P = g_cpart + (size_t)kq * BB * HO;

    for (int base = 0; base < n; base += 8) {
        int R = n - base; if (R > 8) R = 8;
        for (int i = threadIdx.x; i < 8 * KQ; i += 256) {
            int r = i >> 6;
            int k = i & (KQ - 1);
            int rr  = (r < R) ? r : 0;
            int row = g_list[m * BB + base + rr];
            hs[r][k] = hid[row * HH + kq * KQ + k];
            if (k == 0) rows[r] = row;
        }
        __syncthreads();

        float2 acc[8];
#pragma unroll
        for (int r = 0; r < 8; r++) { acc[r].x = 0.f; acc[r].y = 0.f; }

        for (int k = 0; k < KQ; k += 8) {
            float2 w[8];
#pragma unroll
            for (int u = 0; u < 8; u++) w[u] = WoP[(k + u) * (HO / 2)];
#pragma unroll
            for (int u = 0; u < 8; u++) {
#pragma unroll
                for (int r = 0; r < 8; r++) {
                    float x = hs[r][k + u];
                    acc[r].x += x * w[u].x;
                    acc[r].y += x * w[u].y;
                }
            }
        }

        for (int r = 0; r < R; r++) {
            int row = rows[r];
            *(float2*)(P + (size_t)row * HO + col0) = acc[r];
        }
        __syncthreads();
    }
}

// comm epilogue: comm = (p0+p1+p2+p3 + bo[m]) / 7. grid (1024, 256), float4/thread.
__global__ void __launch_bounds__(256) k_commep(
                        const int* __restrict__ mid,
                        const float* __restrict__ bo,
                        float* __restrict__ comm) {
    int row  = blockIdx.x >> 1;
    int half = blockIdx.x & 1;
    int col  = half * (HO / 2) + threadIdx.x * 4;
    int m    = mid[row];

    size_t off = (size_t)row * HO + col;
    float4 p0 = *(const float4*)(g_cpart + off);
    float4 p1 = *(const float4*)(g_cpart + 1ull * BB * HO + off);
    float4 p2 = *(const float4*)(g_cpart + 2ull * BB * HO + off);
    float4 p3 = *(const float4*)(g_cpart + 3ull * BB * HO + off);
    float4 bv = *(const float4*)(bo + m * HO + col);
    float4 o;
    o.x = (p0.x + p1.x + p2.x + p3.x + bv.x) * (1.0f / 7.0f);
    o.y = (p0.y + p1.y + p2.y + p3.y + bv.y) * (1.0f / 7.0f);
    o.z = (p0.z + p1.z + p2.z + p3.z + bv.z) * (1.0f / 7.0f);
    o.w = (p0.w + p1.w + p2.w + p3.w + bv.w) * (1.0f / 7.0f);
    *(float4*)(comm + off) = o;
}

extern "C" void kernel_launch(void* const* d_in, const int* in_sizes, int n_in,
                              void* d_out, int out_size) {
    const float* comm_in  = (const float*)d_in[0];
    const int*   inp      = (const int*)d_in[1];
    const float* prev_hid = (const float*)d_in[2];
    const int*   mid      = (const int*)d_in[4];
    const float* Wc       = (const float*)d_in[5];
    const float* bc       = (const float*)d_in[6];
    const float* Wr       = (const float*)d_in[7];
    const float* br       = (const float*)d_in[8];
    const float* Wa       = (const float*)d_in[9];
    const float* ba       = (const float*)d_in[10];
    const float* Wb       = (const float*)d_in[11];
    const float* bb       = (const float*)d_in[12];
    const float* Wo       = (const float*)d_in[13];
    const float* bo       = (const float*)d_in[14];
    const float* lut      = (const float*)d_in[15];
    const float* enc_bias = (const float*)d_in[16];

    float* out  = (float*)d_out;
    float* act  = out + ACT_OFF;
    float* base = out + BASE_OFF;
    float* hid  = out + HID_OFF;
    float* comm = out + COMM_OFF;

    k_zero<<<1, 32>>>();
    k_prep<<<BB, HH>>>(comm_in, mid);
    k_hidmm<<<dim3(MM, 4, 4), 128>>>(prev_hid, Wc, Wr);
    k_hidact<<<BB, 128>>>(mid, bc, br, lut, inp, enc_bias,
                          Wa, ba, Wb, bb, hid, act, base);
    k_commout<<<dim3(MM, 4, 4), 256>>>(hid, Wo);
    k_commep<<<2 * BB, 256>>>(mid, bo, comm);
}